// round 14
// baseline (speedup 1.0000x reference)
#include <cuda_runtime.h>
#include <cstdint>

#define BB 64
#define TT 512
#define DD 1024
#define KK 32
#define BTK (BB*TT*KK)

// scratch (allowed: __device__ globals, no allocation)
__device__ __align__(16) float g_scratch_logits[BTK];
__device__ __align__(16) float g_wh[KK * DD];   // tf32-rounded W
__device__ __align__(16) float g_wl[KK * DD];   // tf32 residual
__device__ float g_spart[BB];
__device__ int   g_msum[BB];
__device__ int   g_done;
__device__ int   g_flag[256];                   // per (batch, t-octant)

// ---------------------------------------------------------------------------
// helpers
// ---------------------------------------------------------------------------
__device__ __forceinline__ void cpa16(void* dst, const void* src) {
    unsigned s = (unsigned)__cvta_generic_to_shared(dst);
    asm volatile("cp.async.cg.shared.global [%0], [%1], 16;\n" :: "r"(s), "l"(src));
}
__device__ __forceinline__ void cpa4(void* dst, const void* src) {
    unsigned s = (unsigned)__cvta_generic_to_shared(dst);
    asm volatile("cp.async.ca.shared.global [%0], [%1], 4;\n" :: "r"(s), "l"(src));
}
__device__ __forceinline__ void cpa_commit() { asm volatile("cp.async.commit_group;\n"); }
template<int N> __device__ __forceinline__ void cpa_wait() {
    asm volatile("cp.async.wait_group %0;\n" :: "n"(N));
}

typedef unsigned long long ull;
__device__ __forceinline__ ull fma2(ull a, ull b, ull c) {
    ull d; asm("fma.rn.f32x2 %0, %1, %2, %3;" : "=l"(d) : "l"(a), "l"(b), "l"(c));
    return d;
}
__device__ __forceinline__ ull add2(ull a, ull b) {
    ull d; asm("add.rn.f32x2 %0, %1, %2;" : "=l"(d) : "l"(a), "l"(b));
    return d;
}
__device__ __forceinline__ ull pack2(float lo, float hi) {
    ull d; asm("mov.b64 %0, {%1, %2};" : "=l"(d) : "f"(lo), "f"(hi));
    return d;
}
__device__ __forceinline__ float2 unpack2(ull v) {
    float2 f; asm("mov.b64 {%0, %1}, %2;" : "=f"(f.x), "=f"(f.y) : "l"(v));
    return f;
}

__device__ __forceinline__ uint32_t tf32cvt(float x) {
    uint32_t r; asm("cvt.rna.tf32.f32 %0, %1;" : "=r"(r) : "f"(x));
    return r;
}
__device__ __forceinline__ void mma1688(
    float& c0, float& c1, float& c2, float& c3,
    uint32_t a0, uint32_t a1, uint32_t a2, uint32_t a3,
    uint32_t b0, uint32_t b1)
{
    asm volatile(
        "mma.sync.aligned.m16n8k8.row.col.f32.tf32.tf32.f32 "
        "{%0,%1,%2,%3}, {%4,%5,%6,%7}, {%8,%9}, {%0,%1,%2,%3};"
        : "+f"(c0), "+f"(c1), "+f"(c2), "+f"(c3)
        : "r"(a0), "r"(a1), "r"(a2), "r"(a3), "r"(b0), "r"(b1));
}

__device__ __forceinline__ float warpMaxPos(float v) {
    return __uint_as_float(__reduce_max_sync(0xffffffffu, __float_as_uint(v)));
}
__device__ __forceinline__ float warpSumf(float v) {
#pragma unroll
    for (int o = 16; o > 0; o >>= 1)
        v += __shfl_xor_sync(0xffffffffu, v, o);
    return v;
}
__device__ __forceinline__ int warpSumi(int v) {
#pragma unroll
    for (int o = 16; o > 0; o >>= 1)
        v += __shfl_xor_sync(0xffffffffu, v, o);
    return v;
}

// ---------------------------------------------------------------------------
// pre-kernel: W tf32 split + reset flags/counter (runs each graph replay)
// ---------------------------------------------------------------------------
__global__ __launch_bounds__(256) void wsplit_kernel(const float* __restrict__ W)
{
    int i = blockIdx.x * 256 + threadIdx.x;
    if (i == 0) g_done = 0;
    if (i < 256) g_flag[i] = 0;
    if (i < KK * DD) {
        float w = W[i];
        uint32_t h = tf32cvt(w);
        float hf = __uint_as_float(h);
        uint32_t l = tf32cvt(w - hf);
        g_wh[i] = hf;
        g_wl[i] = __uint_as_float(l);
    }
}

// ---------------------------------------------------------------------------
// FUSED kernel, 288 blocks x 256 threads (all co-resident at 2 blocks/SM):
//   bid 0..255  : GEMM role — TF32 3-pass mma, tile 128 rows (batch bid>>2,
//                 t-octant bid&3); releases g_flag[bid] when its tile lands.
//   bid 256..287: CRF role — 2 warps = 2 batches; the measured scan, gated on
//                 octant flags (4 waits per batch). Last warp writes the loss.
// No-deadlock: GEMM never waits on CRF; 288 blocks <= 296 resident slots.
// ---------------------------------------------------------------------------
#define GSTR 36
#define SM_VS   0
#define SM_WHS  55296
#define SM_WLS  69120
#define SM_SZ   82944

__global__ __launch_bounds__(256, 2) void fused_kernel(
    const float* __restrict__ V, const float* __restrict__ bias,
    const int*   __restrict__ mask, const int* __restrict__ targets,
    const float* __restrict__ trans, const float* __restrict__ startT,
    const float* __restrict__ endT,
    float* __restrict__ logits,       // [B,T,K] output (4B aligned ok)
    float* __restrict__ out0, int writeLoss)
{
    __shared__ __align__(16) unsigned char sraw[SM_SZ];
    const int tid = threadIdx.x;

    // =======================================================================
    // GEMM role
    // =======================================================================
    if (blockIdx.x < 256) {
        const int g    = blockIdx.x;
        const int w    = tid >> 5;
        const int lane = tid & 31;
        const int gid  = lane >> 2;
        const int tig  = lane & 3;
        const int rowBase = g * 128;
        const int wr = w * 16;

        float* Vs  = (float*)(sraw + SM_VS);    // stage stride 4608 floats
        float* Whs = (float*)(sraw + SM_WHS);   // stage stride 1152 floats
        float* Wls = (float*)(sraw + SM_WLS);

        float c[4][4];
#pragma unroll
        for (int nt = 0; nt < 4; nt++)
#pragma unroll
            for (int r = 0; r < 4; r++) c[nt][r] = 0.f;

        auto loadChunk = [&](int st, int ch) {
            const int d0 = ch * 32;
#pragma unroll
            for (int p = 0; p < 4; p++) {
                int idx = p * 256 + tid;
                int r = idx >> 3, c4 = idx & 7;
                cpa16(&Vs[st * 4608 + r * GSTR + c4 * 4],
                      &V[(size_t)(rowBase + r) * DD + d0 + c4 * 4]);
            }
            {
                int k = tid >> 3, c4 = tid & 7;
                cpa16(&Whs[st * 1152 + k * GSTR + c4 * 4],
                      &g_wh[k * DD + d0 + c4 * 4]);
                cpa16(&Wls[st * 1152 + k * GSTR + c4 * 4],
                      &g_wl[k * DD + d0 + c4 * 4]);
            }
            cpa_commit();
        };

        loadChunk(0, 0);
        loadChunk(1, 1);

        for (int ch = 0; ch < 32; ch++) {
            cpa_wait<1>();
            __syncthreads();
            if (ch + 2 < 32) loadChunk((ch + 2) % 3, ch + 2);
            else cpa_commit();
            const float* Vst = Vs + (ch % 3) * 4608;
            const uint32_t* Wh = (const uint32_t*)(Whs + (ch % 3) * 1152);
            const uint32_t* Wl = (const uint32_t*)(Wls + (ch % 3) * 1152);

#pragma unroll
            for (int k8 = 0; k8 < 4; k8++) {
                const int ab = (wr + gid) * GSTR + k8 * 8 + tig;
                float a0f = Vst[ab];
                float a1f = Vst[ab + 8 * GSTR];
                float a2f = Vst[ab + 4];
                float a3f = Vst[ab + 8 * GSTR + 4];
                uint32_t ah0 = tf32cvt(a0f), ah1 = tf32cvt(a1f);
                uint32_t ah2 = tf32cvt(a2f), ah3 = tf32cvt(a3f);
                uint32_t al0 = tf32cvt(a0f - __uint_as_float(ah0));
                uint32_t al1 = tf32cvt(a1f - __uint_as_float(ah1));
                uint32_t al2 = tf32cvt(a2f - __uint_as_float(ah2));
                uint32_t al3 = tf32cvt(a3f - __uint_as_float(ah3));

#pragma unroll
                for (int nt = 0; nt < 4; nt++) {
                    const int bb = (nt * 8 + gid) * GSTR + k8 * 8 + tig;
                    uint32_t bh0 = Wh[bb], bh1 = Wh[bb + 4];
                    uint32_t bl0 = Wl[bb], bl1 = Wl[bb + 4];
                    mma1688(c[nt][0], c[nt][1], c[nt][2], c[nt][3],
                            ah0, ah1, ah2, ah3, bh0, bh1);
                    mma1688(c[nt][0], c[nt][1], c[nt][2], c[nt][3],
                            al0, al1, al2, al3, bh0, bh1);
                    mma1688(c[nt][0], c[nt][1], c[nt][2], c[nt][3],
                            ah0, ah1, ah2, ah3, bl0, bl1);
                }
            }
        }

        const size_t r0 = (size_t)(rowBase + wr + gid) * KK;
        const size_t r1 = (size_t)(rowBase + wr + gid + 8) * KK;
#pragma unroll
        for (int nt = 0; nt < 4; nt++) {
            int col = nt * 8 + 2 * tig;
            float b0 = bias[col], b1 = bias[col + 1];
            logits[r0 + col]     = c[nt][0] + b0;
            logits[r0 + col + 1] = c[nt][1] + b1;
            logits[r1 + col]     = c[nt][2] + b0;
            logits[r1 + col + 1] = c[nt][3] + b1;
        }

        // release this (batch, octant) tile
        __threadfence();
        __syncthreads();
        if (tid == 0) atomicExch(&g_flag[g], 1);
        return;
    }

    // =======================================================================
    // CRF role: warps 0,1 scan batches (bid-256)*2 + warp
    // =======================================================================
    const int warp = tid >> 5;
    if (warp >= 2) return;
    const int j = tid & 31;
    const int b = (blockIdx.x - 256) * 2 + warp;
    const unsigned FULL = 0xffffffffu;

    float* Lsw  = (float*)(sraw + warp * 4608);          // [buf*512 + idx]
    float* ashw = (float*)(sraw + warp * 4608 + 4096);   // [pp*32 + j]

    ull ep[16];
#pragma unroll
    for (int p = 0; p < 16; p++) {
        float e0 = __expf(trans[(2 * p) * KK + j]);
        float e1 = __expf(trans[(2 * p + 1) * KK + j]);
        ep[p] = pack2(e0, e1);
    }

    const float* Lb = logits + (size_t)b * TT * KK;
    const int*   mb = mask + (size_t)b * TT;

    unsigned mbits[16];
#pragma unroll
    for (int w2 = 0; w2 < 16; w2++)
        mbits[w2] = __ballot_sync(FULL, mb[w2 * 32 + j] != 0);

    auto waitOct = [&](int oct) {
        volatile int* fp = &g_flag[b * 4 + oct];
        while (*fp == 0) __nanosleep(128);
        __syncwarp();
        __threadfence();                 // acquire producer's stores
    };

    auto loadChunk = [&](int buf, int c) {
        const float* src = Lb + (size_t)c * 512;
#pragma unroll
        for (int q = 0; q < 16; q++)
            cpa4(&Lsw[buf * 512 + q * 32 + j], src + q * 32 + j);
        cpa_commit();
    };

    waitOct(0);                          // chunks 0..7 live in octant 0
    loadChunk(0, 0);
    loadChunk(1, 1);

    float a = 0.f, cl = 0.f;
    int pp = 0;
    const float sj = startT[j];

    for (int c = 0; c < 32; c++) {
        cpa_wait<1>();
        __syncwarp();
        const int cb = c & 1;

        float gg[16];
#pragma unroll
        for (int s = 0; s < 16; s++) gg[s] = Lsw[cb * 512 + s * 32 + j];
        __syncwarp();
        if (c + 2 < 32) {
            if (((c + 2) & 7) == 0) waitOct((c + 2) >> 3);
            loadChunk(cb, c + 2);
        } else cpa_commit();

        const unsigned bits = (mbits[c >> 1] >> ((c & 1) * 16)) & 0xFFFFu;

        if (c == 0) {
            a = __expf(sj + gg[0]);
            ashw[j] = a;
            pp = 0;
        }
#pragma unroll
        for (int s = 0; s < 16; s++) gg[s] = __expf(gg[s]);

#pragma unroll
        for (int s = 0; s < 16; s++) {
            if (c == 0 && s == 0) continue;
            __syncwarp();
            const ulonglong2* ap = (const ulonglong2*)(ashw + pp * 32);
            ull p0 = 0, p1 = 0, p2 = 0, p3 = 0;
#pragma unroll
            for (int i = 0; i < 8; i += 4) {
                ulonglong2 q0 = ap[i + 0];
                ulonglong2 q1 = ap[i + 1];
                ulonglong2 q2 = ap[i + 2];
                ulonglong2 q3 = ap[i + 3];
                p0 = fma2(q0.x, ep[2 * i + 0], p0);
                p0 = fma2(q0.y, ep[2 * i + 1], p0);
                p1 = fma2(q1.x, ep[2 * i + 2], p1);
                p1 = fma2(q1.y, ep[2 * i + 3], p1);
                p2 = fma2(q2.x, ep[2 * i + 4], p2);
                p2 = fma2(q2.y, ep[2 * i + 5], p2);
                p3 = fma2(q3.x, ep[2 * i + 6], p3);
                p3 = fma2(q3.y, ep[2 * i + 7], p3);
            }
            ull t = add2(add2(p0, p1), add2(p2, p3));
            float2 f = unpack2(t);
            float dot = f.x + f.y;
            if ((bits >> s) & 1u) a = dot * gg[s];
            if ((s & 7) == 7) {
                float Mx = warpMaxPos(a);
                a = __fdividef(a, Mx);
                cl += __logf(Mx);
            }
            ashw[(pp ^ 1) * 32 + j] = a;
            pp ^= 1;
        }
    }

    float S = warpSumf(a * __expf(endT[j]));
    float partition = cl + __logf(S);

    // ---- gold path score ----
    float emit_s = 0.f, trans_s = 0.f;
    int msum = 0;
    for (int t = j; t < TT; t += 32) {
        int tg = targets[(size_t)b * TT + t];
        int mk = mb[t];
        emit_s += Lb[(size_t)t * KK + tg] * (float)mk;
        if (t >= 1) {
            int tgp = targets[(size_t)b * TT + t - 1];
            trans_s += trans[tgp * KK + tg] * (float)mk;
        }
        msum += mk;
    }
    emit_s  = warpSumf(emit_s);
    trans_s = warpSumf(trans_s);
    msum    = warpSumi(msum);

    if (j == 0) {
        int last = msum - 1;
        int t0 = targets[(size_t)b * TT];
        int tl = targets[(size_t)b * TT + last];
        float score = startT[t0] + emit_s + trans_s + endT[tl];
        g_spart[b] = score - partition;
        g_msum[b]  = msum;
    }

    // ---- last finished warp computes the loss ----
    __threadfence();
    int lastw = 0;
    if (j == 0) lastw = (atomicAdd(&g_done, 1) == BB - 1) ? 1 : 0;
    lastw = __shfl_sync(FULL, lastw, 0);
    if (lastw) {
        __threadfence();
        float sp = g_spart[j] + g_spart[j + 32];
        int   ms = g_msum[j]  + g_msum[j + 32];
        sp = warpSumf(sp);
        ms = warpSumi(ms);
        if (j == 0 && writeLoss) out0[0] = -sp / (float)ms;
    }
}

// ---------------------------------------------------------------------------
extern "C" void kernel_launch(void* const* d_in, const int* in_sizes, int n_in,
                              void* d_out, int out_size)
{
    const float* V       = (const float*)d_in[0];
    const int*   mask    = (const int*)  d_in[1];
    const int*   targets = (const int*)  d_in[2];
    const float* W       = (const float*)d_in[3];
    const float* bias    = (const float*)d_in[4];
    const float* trans   = (const float*)d_in[5];
    const float* startT  = (const float*)d_in[6];
    const float* endT    = (const float*)d_in[7];
    float* out = (float*)d_out;

    void* p = nullptr;
    cudaGetSymbolAddress(&p, g_scratch_logits);
    float* scratch = (float*)p;

    const int loff = out_size - BTK;   // (loss, logits) concat
    float* outLogits = (loff >= 0) ? (out + loff) : scratch;

    wsplit_kernel<<<(KK * DD + 255) / 256, 256>>>(W);
    fused_kernel<<<288, 256>>>(V, bias, mask, targets, trans, startT, endT,
                               outLogits, out, (loff >= 1) ? 1 : 0);
}

// round 15
// speedup vs baseline: 1.0294x; 1.0294x over previous
#include <cuda_runtime.h>
#include <cstdint>

#define BB 64
#define TT 512
#define DD 1024
#define KK 32
#define BTK (BB*TT*KK)

// scratch (allowed: __device__ globals, no allocation)
__device__ __align__(16) float g_scratch_logits[BTK];
__device__ __align__(16) float g_wh[KK * DD];   // tf32-rounded W
__device__ __align__(16) float g_wl[KK * DD];   // tf32 residual
__device__ float g_spart[BB];
__device__ int   g_msum[BB];
__device__ int   g_done;
__device__ int   g_flag[256];                   // per (batch*4 + t-octant)

// ---------------------------------------------------------------------------
// helpers
// ---------------------------------------------------------------------------
__device__ __forceinline__ void cpa16(void* dst, const void* src) {
    unsigned s = (unsigned)__cvta_generic_to_shared(dst);
    asm volatile("cp.async.cg.shared.global [%0], [%1], 16;\n" :: "r"(s), "l"(src));
}
__device__ __forceinline__ void cpa4(void* dst, const void* src) {
    unsigned s = (unsigned)__cvta_generic_to_shared(dst);
    asm volatile("cp.async.ca.shared.global [%0], [%1], 4;\n" :: "r"(s), "l"(src));
}
__device__ __forceinline__ void cpa_commit() { asm volatile("cp.async.commit_group;\n"); }
template<int N> __device__ __forceinline__ void cpa_wait() {
    asm volatile("cp.async.wait_group %0;\n" :: "n"(N));
}

typedef unsigned long long ull;
__device__ __forceinline__ ull fma2(ull a, ull b, ull c) {
    ull d; asm("fma.rn.f32x2 %0, %1, %2, %3;" : "=l"(d) : "l"(a), "l"(b), "l"(c));
    return d;
}
__device__ __forceinline__ ull add2(ull a, ull b) {
    ull d; asm("add.rn.f32x2 %0, %1, %2;" : "=l"(d) : "l"(a), "l"(b));
    return d;
}
__device__ __forceinline__ ull pack2(float lo, float hi) {
    ull d; asm("mov.b64 %0, {%1, %2};" : "=l"(d) : "f"(lo), "f"(hi));
    return d;
}
__device__ __forceinline__ float2 unpack2(ull v) {
    float2 f; asm("mov.b64 {%0, %1}, %2;" : "=f"(f.x), "=f"(f.y) : "l"(v));
    return f;
}

__device__ __forceinline__ uint32_t tf32cvt(float x) {
    uint32_t r; asm("cvt.rna.tf32.f32 %0, %1;" : "=r"(r) : "f"(x));
    return r;
}
__device__ __forceinline__ void mma1688(
    float& c0, float& c1, float& c2, float& c3,
    uint32_t a0, uint32_t a1, uint32_t a2, uint32_t a3,
    uint32_t b0, uint32_t b1)
{
    asm volatile(
        "mma.sync.aligned.m16n8k8.row.col.f32.tf32.tf32.f32 "
        "{%0,%1,%2,%3}, {%4,%5,%6,%7}, {%8,%9}, {%0,%1,%2,%3};"
        : "+f"(c0), "+f"(c1), "+f"(c2), "+f"(c3)
        : "r"(a0), "r"(a1), "r"(a2), "r"(a3), "r"(b0), "r"(b1));
}

__device__ __forceinline__ float warpMaxPos(float v) {
    return __uint_as_float(__reduce_max_sync(0xffffffffu, __float_as_uint(v)));
}
__device__ __forceinline__ float warpSumf(float v) {
#pragma unroll
    for (int o = 16; o > 0; o >>= 1)
        v += __shfl_xor_sync(0xffffffffu, v, o);
    return v;
}
__device__ __forceinline__ int warpSumi(int v) {
#pragma unroll
    for (int o = 16; o > 0; o >>= 1)
        v += __shfl_xor_sync(0xffffffffu, v, o);
    return v;
}

// ---------------------------------------------------------------------------
// pre-kernel: W tf32 split + reset flags/counter (runs each graph replay)
// ---------------------------------------------------------------------------
__global__ __launch_bounds__(256) void wsplit_kernel(const float* __restrict__ W)
{
    int i = blockIdx.x * 256 + threadIdx.x;
    if (i == 0) g_done = 0;
    if (i < 256) g_flag[i] = 0;
    if (i < KK * DD) {
        float w = W[i];
        uint32_t h = tf32cvt(w);
        float hf = __uint_as_float(h);
        uint32_t l = tf32cvt(w - hf);
        g_wh[i] = hf;
        g_wl[i] = __uint_as_float(l);
    }
}

// ---------------------------------------------------------------------------
// FUSED kernel, 160 blocks x 256 threads (all co-resident at 2 blocks/SM):
//   bid 0..127  : GEMM role, PERSISTENT over 2 tiles in octant-major order:
//                 tidx = bid, then bid+128; oct = tidx>>6, batch = tidx&63,
//                 rowBase = (batch*4+oct)*128. So octants {0,1} of ALL
//                 batches land at ~T/2, octants {2,3} at ~T -> staggered
//                 production for the consumer.
//   bid 128..159: CRF role, 2 warps = 2 batches each; scan gated per-octant
//                 on g_flag[batch*4+oct]. Last warp writes the loss.
// No-deadlock: GEMM never waits on CRF; 160 blocks <= 296 resident slots.
// ---------------------------------------------------------------------------
#define GSTR 36
#define SM_VS   0
#define SM_WHS  55296
#define SM_WLS  69120
#define SM_SZ   82944

__global__ __launch_bounds__(256, 2) void fused_kernel(
    const float* __restrict__ V, const float* __restrict__ bias,
    const int*   __restrict__ mask, const int* __restrict__ targets,
    const float* __restrict__ trans, const float* __restrict__ startT,
    const float* __restrict__ endT,
    float* __restrict__ logits,       // [B,T,K] output (4B aligned ok)
    float* __restrict__ out0, int writeLoss)
{
    __shared__ __align__(16) unsigned char sraw[SM_SZ];
    const int tid = threadIdx.x;

    // =======================================================================
    // GEMM role: two tiles, octant-major order
    // =======================================================================
    if (blockIdx.x < 128) {
        const int w    = tid >> 5;
        const int lane = tid & 31;
        const int gid  = lane >> 2;
        const int tig  = lane & 3;
        const int wr = w * 16;

        float* Vs  = (float*)(sraw + SM_VS);    // stage stride 4608 floats
        float* Whs = (float*)(sraw + SM_WHS);   // stage stride 1152 floats
        float* Wls = (float*)(sraw + SM_WLS);

        for (int pass = 0; pass < 2; pass++) {
            const int tidx  = blockIdx.x + pass * 128;
            const int oct   = tidx >> 6;
            const int batch = tidx & 63;
            const int rowBase = (batch * 4 + oct) * 128;

            float c[4][4];
#pragma unroll
            for (int nt = 0; nt < 4; nt++)
#pragma unroll
                for (int r = 0; r < 4; r++) c[nt][r] = 0.f;

            auto loadChunk = [&](int st, int ch) {
                const int d0 = ch * 32;
#pragma unroll
                for (int p = 0; p < 4; p++) {
                    int idx = p * 256 + tid;
                    int r = idx >> 3, c4 = idx & 7;
                    cpa16(&Vs[st * 4608 + r * GSTR + c4 * 4],
                          &V[(size_t)(rowBase + r) * DD + d0 + c4 * 4]);
                }
                {
                    int k = tid >> 3, c4 = tid & 7;
                    cpa16(&Whs[st * 1152 + k * GSTR + c4 * 4],
                          &g_wh[k * DD + d0 + c4 * 4]);
                    cpa16(&Wls[st * 1152 + k * GSTR + c4 * 4],
                          &g_wl[k * DD + d0 + c4 * 4]);
                }
                cpa_commit();
            };

            loadChunk(0, 0);
            loadChunk(1, 1);

            for (int ch = 0; ch < 32; ch++) {
                cpa_wait<1>();
                __syncthreads();
                if (ch + 2 < 32) loadChunk((ch + 2) % 3, ch + 2);
                else cpa_commit();
                const float* Vst = Vs + (ch % 3) * 4608;
                const uint32_t* Wh = (const uint32_t*)(Whs + (ch % 3) * 1152);
                const uint32_t* Wl = (const uint32_t*)(Wls + (ch % 3) * 1152);

#pragma unroll
                for (int k8 = 0; k8 < 4; k8++) {
                    const int ab = (wr + gid) * GSTR + k8 * 8 + tig;
                    float a0f = Vst[ab];
                    float a1f = Vst[ab + 8 * GSTR];
                    float a2f = Vst[ab + 4];
                    float a3f = Vst[ab + 8 * GSTR + 4];
                    uint32_t ah0 = tf32cvt(a0f), ah1 = tf32cvt(a1f);
                    uint32_t ah2 = tf32cvt(a2f), ah3 = tf32cvt(a3f);
                    uint32_t al0 = tf32cvt(a0f - __uint_as_float(ah0));
                    uint32_t al1 = tf32cvt(a1f - __uint_as_float(ah1));
                    uint32_t al2 = tf32cvt(a2f - __uint_as_float(ah2));
                    uint32_t al3 = tf32cvt(a3f - __uint_as_float(ah3));

#pragma unroll
                    for (int nt = 0; nt < 4; nt++) {
                        const int bb = (nt * 8 + gid) * GSTR + k8 * 8 + tig;
                        uint32_t bh0 = Wh[bb], bh1 = Wh[bb + 4];
                        uint32_t bl0 = Wl[bb], bl1 = Wl[bb + 4];
                        mma1688(c[nt][0], c[nt][1], c[nt][2], c[nt][3],
                                ah0, ah1, ah2, ah3, bh0, bh1);
                        mma1688(c[nt][0], c[nt][1], c[nt][2], c[nt][3],
                                al0, al1, al2, al3, bh0, bh1);
                        mma1688(c[nt][0], c[nt][1], c[nt][2], c[nt][3],
                                ah0, ah1, ah2, ah3, bl0, bl1);
                    }
                }
            }

            const size_t r0 = (size_t)(rowBase + wr + gid) * KK;
            const size_t r1 = (size_t)(rowBase + wr + gid + 8) * KK;
#pragma unroll
            for (int nt = 0; nt < 4; nt++) {
                int col = nt * 8 + 2 * tig;
                float b0 = bias[col], b1 = bias[col + 1];
                logits[r0 + col]     = c[nt][0] + b0;
                logits[r0 + col + 1] = c[nt][1] + b1;
                logits[r1 + col]     = c[nt][2] + b0;
                logits[r1 + col + 1] = c[nt][3] + b1;
            }

            // release this (batch, octant) tile
            __threadfence();
            __syncthreads();
            if (tid == 0) atomicExch(&g_flag[batch * 4 + oct], 1);
        }
        return;
    }

    // =======================================================================
    // CRF role: warps 0,1 scan batches (bid-128)*2 + warp
    // =======================================================================
    const int warp = tid >> 5;
    if (warp >= 2) return;
    const int j = tid & 31;
    const int b = (blockIdx.x - 128) * 2 + warp;
    const unsigned FULL = 0xffffffffu;

    float* Lsw  = (float*)(sraw + warp * 4608);          // [buf*512 + idx]
    float* ashw = (float*)(sraw + warp * 4608 + 4096);   // [pp*32 + j]

    ull ep[16];
#pragma unroll
    for (int p = 0; p < 16; p++) {
        float e0 = __expf(trans[(2 * p) * KK + j]);
        float e1 = __expf(trans[(2 * p + 1) * KK + j]);
        ep[p] = pack2(e0, e1);
    }

    const float* Lb = logits + (size_t)b * TT * KK;
    const int*   mb = mask + (size_t)b * TT;

    unsigned mbits[16];
#pragma unroll
    for (int w2 = 0; w2 < 16; w2++)
        mbits[w2] = __ballot_sync(FULL, mb[w2 * 32 + j] != 0);

    auto waitOct = [&](int oct) {
        volatile int* fp = &g_flag[b * 4 + oct];
        while (*fp == 0) __nanosleep(128);
        __syncwarp();
        __threadfence();                 // acquire producer's stores
    };

    auto loadChunk = [&](int buf, int c) {
        const float* src = Lb + (size_t)c * 512;
#pragma unroll
        for (int q = 0; q < 16; q++)
            cpa4(&Lsw[buf * 512 + q * 32 + j], src + q * 32 + j);
        cpa_commit();
    };

    waitOct(0);                          // chunks 0..7 live in octant 0
    loadChunk(0, 0);
    loadChunk(1, 1);

    float a = 0.f, cl = 0.f;
    int pp = 0;
    const float sj = startT[j];

    for (int c = 0; c < 32; c++) {
        cpa_wait<1>();
        __syncwarp();
        const int cb = c & 1;

        float gg[16];
#pragma unroll
        for (int s = 0; s < 16; s++) gg[s] = Lsw[cb * 512 + s * 32 + j];
        __syncwarp();
        if (c + 2 < 32) {
            if (((c + 2) & 7) == 0) waitOct((c + 2) >> 3);
            loadChunk(cb, c + 2);
        } else cpa_commit();

        const unsigned bits = (mbits[c >> 1] >> ((c & 1) * 16)) & 0xFFFFu;

        if (c == 0) {
            a = __expf(sj + gg[0]);
            ashw[j] = a;
            pp = 0;
        }
#pragma unroll
        for (int s = 0; s < 16; s++) gg[s] = __expf(gg[s]);

#pragma unroll
        for (int s = 0; s < 16; s++) {
            if (c == 0 && s == 0) continue;
            __syncwarp();
            const ulonglong2* ap = (const ulonglong2*)(ashw + pp * 32);
            ull p0 = 0, p1 = 0, p2 = 0, p3 = 0;
#pragma unroll
            for (int i = 0; i < 8; i += 4) {
                ulonglong2 q0 = ap[i + 0];
                ulonglong2 q1 = ap[i + 1];
                ulonglong2 q2 = ap[i + 2];
                ulonglong2 q3 = ap[i + 3];
                p0 = fma2(q0.x, ep[2 * i + 0], p0);
                p0 = fma2(q0.y, ep[2 * i + 1], p0);
                p1 = fma2(q1.x, ep[2 * i + 2], p1);
                p1 = fma2(q1.y, ep[2 * i + 3], p1);
                p2 = fma2(q2.x, ep[2 * i + 4], p2);
                p2 = fma2(q2.y, ep[2 * i + 5], p2);
                p3 = fma2(q3.x, ep[2 * i + 6], p3);
                p3 = fma2(q3.y, ep[2 * i + 7], p3);
            }
            ull t = add2(add2(p0, p1), add2(p2, p3));
            float2 f = unpack2(t);
            float dot = f.x + f.y;
            if ((bits >> s) & 1u) a = dot * gg[s];
            if ((s & 7) == 7) {
                float Mx = warpMaxPos(a);
                a = __fdividef(a, Mx);
                cl += __logf(Mx);
            }
            ashw[(pp ^ 1) * 32 + j] = a;
            pp ^= 1;
        }
    }

    float S = warpSumf(a * __expf(endT[j]));
    float partition = cl + __logf(S);

    // ---- gold path score ----
    float emit_s = 0.f, trans_s = 0.f;
    int msum = 0;
    for (int t = j; t < TT; t += 32) {
        int tg = targets[(size_t)b * TT + t];
        int mk = mb[t];
        emit_s += Lb[(size_t)t * KK + tg] * (float)mk;
        if (t >= 1) {
            int tgp = targets[(size_t)b * TT + t - 1];
            trans_s += trans[tgp * KK + tg] * (float)mk;
        }
        msum += mk;
    }
    emit_s  = warpSumf(emit_s);
    trans_s = warpSumf(trans_s);
    msum    = warpSumi(msum);

    if (j == 0) {
        int last = msum - 1;
        int t0 = targets[(size_t)b * TT];
        int tl = targets[(size_t)b * TT + last];
        float score = startT[t0] + emit_s + trans_s + endT[tl];
        g_spart[b] = score - partition;
        g_msum[b]  = msum;
    }

    // ---- last finished warp computes the loss ----
    __threadfence();
    int lastw = 0;
    if (j == 0) lastw = (atomicAdd(&g_done, 1) == BB - 1) ? 1 : 0;
    lastw = __shfl_sync(FULL, lastw, 0);
    if (lastw) {
        __threadfence();
        float sp = g_spart[j] + g_spart[j + 32];
        int   ms = g_msum[j]  + g_msum[j + 32];
        sp = warpSumf(sp);
        ms = warpSumi(ms);
        if (j == 0 && writeLoss) out0[0] = -sp / (float)ms;
    }
}

// ---------------------------------------------------------------------------
extern "C" void kernel_launch(void* const* d_in, const int* in_sizes, int n_in,
                              void* d_out, int out_size)
{
    const float* V       = (const float*)d_in[0];
    const int*   mask    = (const int*)  d_in[1];
    const int*   targets = (const int*)  d_in[2];
    const float* W       = (const float*)d_in[3];
    const float* bias    = (const float*)d_in[4];
    const float* trans   = (const float*)d_in[5];
    const float* startT  = (const float*)d_in[6];
    const float* endT    = (const float*)d_in[7];
    float* out = (float*)d_out;

    void* p = nullptr;
    cudaGetSymbolAddress(&p, g_scratch_logits);
    float* scratch = (float*)p;

    const int loff = out_size - BTK;   // (loss, logits) concat
    float* outLogits = (loff >= 0) ? (out + loff) : scratch;

    wsplit_kernel<<<(KK * DD + 255) / 256, 256>>>(W);
    fused_kernel<<<160, 256>>>(V, bias, mask, targets, trans, startT, endT,
                               outLogits, out, (loff >= 1) ? 1 : 0);
}